// round 14
// baseline (speedup 1.0000x reference)
#include <cuda_runtime.h>
#include <cuda_fp16.h>
#include <math.h>
#include <stdint.h>

#define NTOK   4096
#define DIM    1024
#define NEXP   8
#define HIDDEN 4096

#define BM 128
#define BN 128
#define BKH 64            // K halfs per k-tile
#define NT 256
#define ROWA 144          // A SMEM row stride bytes
#define ROWBB 272         // B SMEM row stride bytes

#define TILE_A  (BM * ROWA)          // 18432
#define TILE_BB (BKH * ROWBB)        // 17408
#define STAGE_B (TILE_A + TILE_BB)   // 35840
#define NSTAGE  3
#define ROWE 272                     // epilogue staging row pitch (bytes)

#define GATE_BLOCKS 512
#define W1CVT_BLOCKS 2048
#define G1_BLOCKS  8192              // 32m * 32n * 8e
#define CVT_CHUNKS 8192u             // W2 cvt: 8192 chunks x 1024 float4

// ---------------- scratch (__device__ statics — alloc-free) ----------------
__device__ int    g_cnt[NEXP];
__device__ unsigned int g_cvt;
__device__ int    g_list[NEXP][NTOK];
__device__ float  g_gw[NEXP][NTOK];
__device__ __half g_xh[(size_t)NTOK * DIM];
__device__ __half g_h[(size_t)NTOK * 2 * HIDDEN];
__device__ __half g_W1h[(size_t)NEXP * DIM * HIDDEN];     // [e][k][n] fp16
__device__ __half g_W2h[(size_t)NEXP * HIDDEN * DIM];     // [e][k][n] fp16

// ---------------- helpers ----------------
__device__ __forceinline__ uint32_t smem_u32(const void* p) {
    uint32_t a;
    asm("{ .reg .u64 t; cvta.to.shared.u64 t, %1; cvt.u32.u64 %0, t; }" : "=r"(a) : "l"(p));
    return a;
}
__device__ __forceinline__ void cp_async16(uint32_t dst, const void* src) {
    asm volatile("cp.async.cg.shared.global [%0], [%1], 16;" :: "r"(dst), "l"(src));
}
#define CP_COMMIT() asm volatile("cp.async.commit_group;" ::: "memory")
#define CP_WAIT2()  asm volatile("cp.async.wait_group 2;" ::: "memory")

__device__ __forceinline__ void ldsm_x4(uint32_t* r, uint32_t addr) {
    asm volatile("ldmatrix.sync.aligned.m8n8.x4.shared.b16 {%0,%1,%2,%3}, [%4];"
                 : "=r"(r[0]), "=r"(r[1]), "=r"(r[2]), "=r"(r[3]) : "r"(addr));
}
__device__ __forceinline__ void ldsm_x4_t(uint32_t* r, uint32_t addr) {
    asm volatile("ldmatrix.sync.aligned.m8n8.x4.trans.shared.b16 {%0,%1,%2,%3}, [%4];"
                 : "=r"(r[0]), "=r"(r[1]), "=r"(r[2]), "=r"(r[3]) : "r"(addr));
}
__device__ __forceinline__ void mma_f16(float* d, const uint32_t* a, uint32_t b0, uint32_t b1) {
    asm volatile(
        "mma.sync.aligned.m16n8k16.row.col.f32.f16.f16.f32 "
        "{%0,%1,%2,%3}, {%4,%5,%6,%7}, {%8,%9}, {%0,%1,%2,%3};"
        : "+f"(d[0]), "+f"(d[1]), "+f"(d[2]), "+f"(d[3])
        : "r"(a[0]), "r"(a[1]), "r"(a[2]), "r"(a[3]), "r"(b0), "r"(b1));
}

// ---------------- kernel 0: reset counters ----------------
__global__ void zero_cnt_kernel() {
    if (threadIdx.x < NEXP) g_cnt[threadIdx.x] = 0;
    if (threadIdx.x == 0)   g_cvt = 0u;
}

// ---------------- prep: gate(+x cvt + out zero) | W1 straight cvt ----------------
__global__ void prep_kernel(const float* __restrict__ x,
                            const float* __restrict__ Wg,
                            const float* __restrict__ bg,
                            const float* __restrict__ W1,
                            float* __restrict__ out) {
    const int bid = blockIdx.x;
    const int tid = threadIdx.x;

    if (bid >= GATE_BLOCKS) {
        size_t base = (size_t)(bid - GATE_BLOCKS) * 16384 + (size_t)tid * 4;
#pragma unroll
        for (int j = 0; j < 16; j++) {
            size_t idx = base + (size_t)j * 1024;
            float4 v = *(const float4*)(W1 + idx);
            __half2 h0 = __floats2half2_rn(v.x, v.y);
            __half2 h1 = __floats2half2_rn(v.z, v.w);
            *(uint2*)(g_W1h + idx) = make_uint2(*(uint32_t*)&h0, *(uint32_t*)&h1);
        }
        return;
    }

    int warp = bid * 8 + (tid >> 5);
    int lane = tid & 31;

    const float4* xr4 = (const float4*)(x + (size_t)warp * DIM);
    __half2* xo = (__half2*)(g_xh + (size_t)warp * DIM);
    float4* oz = (float4*)(out + (size_t)warp * DIM);

    float acc[NEXP];
#pragma unroll
    for (int e = 0; e < NEXP; e++) acc[e] = 0.f;

#pragma unroll
    for (int it = 0; it < 8; it++) {
        int i4 = lane + it * 32;
        float4 xv = xr4[i4];
        xo[2 * i4]     = __floats2half2_rn(xv.x, xv.y);
        xo[2 * i4 + 1] = __floats2half2_rn(xv.z, xv.w);
        oz[i4] = make_float4(0.f, 0.f, 0.f, 0.f);
        const float* xs = (const float*)&xv;
#pragma unroll
        for (int c = 0; c < 4; c++) {
            float v = xs[c];
            const float4* w = reinterpret_cast<const float4*>(Wg + (size_t)(i4 * 4 + c) * NEXP);
            float4 w0 = w[0], w1 = w[1];
            acc[0] = fmaf(v, w0.x, acc[0]); acc[1] = fmaf(v, w0.y, acc[1]);
            acc[2] = fmaf(v, w0.z, acc[2]); acc[3] = fmaf(v, w0.w, acc[3]);
            acc[4] = fmaf(v, w1.x, acc[4]); acc[5] = fmaf(v, w1.y, acc[5]);
            acc[6] = fmaf(v, w1.z, acc[6]); acc[7] = fmaf(v, w1.w, acc[7]);
        }
    }
#pragma unroll
    for (int off = 16; off > 0; off >>= 1)
#pragma unroll
        for (int e = 0; e < NEXP; e++)
            acc[e] += __shfl_xor_sync(0xffffffffu, acc[e], off);

    if (lane == 0) {
        float lg[NEXP], mx = -1e30f;
#pragma unroll
        for (int e = 0; e < NEXP; e++) { lg[e] = acc[e] + bg[e]; mx = fmaxf(mx, lg[e]); }
        float p[NEXP], s = 0.f;
#pragma unroll
        for (int e = 0; e < NEXP; e++) { p[e] = expf(lg[e] - mx); s += p[e]; }
        float inv = 1.f / s;
        int i0 = 0;
#pragma unroll
        for (int e = 1; e < NEXP; e++) if (p[e] > p[i0]) i0 = e;
        int i1 = (i0 == 0) ? 1 : 0;
#pragma unroll
        for (int e = 0; e < NEXP; e++) if (e != i0 && p[e] > p[i1]) i1 = e;

        int pos0 = atomicAdd(&g_cnt[i0], 1);
        g_list[i0][pos0] = warp * 2 + 0;  g_gw[i0][pos0] = p[i0] * inv;
        int pos1 = atomicAdd(&g_cnt[i1], 1);
        g_list[i1][pos1] = warp * 2 + 1;  g_gw[i1][pos1] = p[i1] * inv;
    }
}

// ---------------- fp16 mma GEMM: 8 warps (64x32 tiles), 3-stage pipeline ----------------
// MODE 0: A = gathered g_xh, B = g_W1h, epi: half(relu(acc+b1)) -> SMEM -> coalesced g_h
//         W2 fp32->fp16 cvt stuffed into the mainloop's idle issue slots.
// MODE 1: A = gathered g_h,  B = g_W2h, epi: atomicAdd(out, gw*(acc+b2))
template<int MODE, int KDIM, int NCOLS, int LOGN>
__global__ void __launch_bounds__(NT, 2)
moe_mma(const __half* __restrict__ Asrc, const __half* __restrict__ Wh,
        const float* __restrict__ bias, float* __restrict__ out,
        const float* __restrict__ cvt_src, __half* __restrict__ cvt_dst) {
    const int bid = blockIdx.x;
    const int tid = threadIdx.x;

    const int e   = bid >> (5 + LOGN);
    const int cnt = g_cnt[e];
    const int m0  = (bid & 31) * BM;
    if (m0 >= cnt) return;
    const int gn0 = ((bid >> 5) & ((1 << LOGN) - 1)) * BN;

    extern __shared__ char smem[];
    int*      s_row = (int*)smem;                 // [128] @ 0
    float*    s_gw  = (float*)(smem + 512);       // [128] @ 512
    unsigned* s_cvt = (unsigned*)(smem + 1024);   // @ 1024

    const int wid  = tid >> 5, lane = tid & 31;
    const int wm   = (wid >> 2) * 64;          // 0,64
    const int wn   = (wid & 3) * 32;           // 0,32,64,96
    const int g    = lane >> 2;
    const int tg   = lane & 3;

    for (int i = tid; i < BM; i += NT) {
        int r = m0 + i;
        if (r < cnt) { s_row[i] = g_list[e][r]; s_gw[i] = g_gw[e][r]; }
        else         { s_row[i] = -1;           s_gw[i] = 0.f; }
    }
    if (MODE == 0 && tid == 0) *s_cvt = atomicAdd(&g_cvt, 4u);
    __syncthreads();
    const unsigned cvt_base = (MODE == 0) ? *s_cvt : 0u;

    const uint32_t tiles_b = smem_u32(smem) + 1280;

    // A loader: 4 chunks of 16B; chunk i -> row lrow+32i, col c8
    const int lrow = tid >> 3, c8 = tid & 7;
    uint32_t a_off[4];
#pragma unroll
    for (int i = 0; i < 4; i++) {
        int p = s_row[lrow + i * 32];
        int arow = (p >= 0) ? (MODE == 0 ? (p >> 1) : p) : 0;
        a_off[i] = (uint32_t)arow * KDIM + c8 * 8;
    }
    const uint32_t a_dst0 = (uint32_t)(lrow * ROWA + c8 * 16);
    const uint32_t rstepA = 32 * ROWA;

    // B loader (K-major): 4 chunks; chunk i -> k-row brow+16i
    const int brow = tid >> 4, bc16 = tid & 15;
    const __half* b_base = Wh + ((size_t)e * KDIM + brow) * NCOLS + gn0 + bc16 * 8;
    const uint32_t b_dst0 = (uint32_t)(TILE_A + brow * ROWBB + bc16 * 16);
    const uint32_t bstep  = 16 * ROWBB;

    // LDSM lane addressing
    const uint32_t a_lane = (uint32_t)((lane & 15) * ROWA + (lane >> 4) * 16);
    const uint32_t bt_row = (uint32_t)(lane & 15);
    const uint32_t bt_col = (uint32_t)(((lane >> 4) & 1) * 16);

    float acc[4][4][4];
#pragma unroll
    for (int i = 0; i < 4; i++)
#pragma unroll
        for (int j = 0; j < 4; j++)
#pragma unroll
            for (int q = 0; q < 4; q++) acc[i][j][q] = 0.f;

    const int KT = KDIM / BKH;

    // prologue: stages 0 and 1
#pragma unroll
    for (int st = 0; st < 2; st++) {
        const uint32_t sb = tiles_b + st * STAGE_B;
        const int kk = st * BKH;
#pragma unroll
        for (int i = 0; i < 4; i++) {
            cp_async16(sb + a_dst0 + i * rstepA, Asrc + a_off[i] + kk);
            cp_async16(sb + b_dst0 + i * bstep,
                       b_base + (size_t)(kk + 16 * i) * NCOLS);
        }
        CP_COMMIT();
    }

    int stc = 0;
    int stp = 2;
#pragma unroll 1
    for (int t = 0; t < KT; ++t) {
        // ---- stuffed W2 cvt: load early (latency hides under the k-iter) ----
        float4 vv;
        bool do_cvt = false;
        size_t fidx = 0;
        if (MODE == 0) {
            unsigned ck = cvt_base + (unsigned)(t >> 2);
            if (ck < CVT_CHUNKS) {
                fidx = (size_t)ck * 1024 + (size_t)(t & 3) * 256 + tid;
                vv = ((const float4*)cvt_src)[fidx];
                do_cvt = true;
            }
        }

        if (t + 2 < KT) {
            const uint32_t sb = tiles_b + stp * STAGE_B;
            const int k2 = (t + 2) * BKH;
#pragma unroll
            for (int i = 0; i < 4; i++) {
                cp_async16(sb + a_dst0 + i * rstepA, Asrc + a_off[i] + k2);
                cp_async16(sb + b_dst0 + i * bstep,
                           b_base + (size_t)(k2 + 16 * i) * NCOLS);
            }
        }
        CP_COMMIT();
        CP_WAIT2();
        __syncthreads();

        const uint32_t As_b = tiles_b + stc * STAGE_B;
        const uint32_t Bs_b = As_b + TILE_A;
#pragma unroll
        for (int s = 0; s < 4; s++) {
            uint32_t af[4][4];
#pragma unroll
            for (int i = 0; i < 4; i++)
                ldsm_x4(af[i], As_b + (uint32_t)(wm + 16 * i) * ROWA + s * 32 + a_lane);
            uint32_t bf[2][4];
#pragma unroll
            for (int j2 = 0; j2 < 2; j2++)
                ldsm_x4_t(bf[j2], Bs_b + (uint32_t)(s * 16 + bt_row) * ROWBB
                                   + (uint32_t)(wn * 2 + j2 * 32) + bt_col);
#pragma unroll
            for (int i = 0; i < 4; i++)
#pragma unroll
                for (int j2 = 0; j2 < 2; j2++) {
                    mma_f16(acc[i][2 * j2],     af[i], bf[j2][0], bf[j2][1]);
                    mma_f16(acc[i][2 * j2 + 1], af[i], bf[j2][2], bf[j2][3]);
                }
        }

        // ---- stuffed W2 cvt: convert + store after compute ----
        if (MODE == 0 && do_cvt) {
            __half2 h0 = __floats2half2_rn(vv.x, vv.y);
            __half2 h1 = __floats2half2_rn(vv.z, vv.w);
            ((uint2*)cvt_dst)[fidx] = make_uint2(*(uint32_t*)&h0, *(uint32_t*)&h1);
        }

        __syncthreads();
        stc = (stc == NSTAGE - 1) ? 0 : stc + 1;
        stp = (stp == NSTAGE - 1) ? 0 : stp + 1;
    }

    // ---------------- epilogue ----------------
    if (MODE == 0) {
        // stage bias+relu+fp16 results in SMEM (conflict-free: word=(4g+tg)%32),
        // then write fully coalesced 128B runs per token row.
        const uint32_t ep = tiles_b;   // reuse stage-0 tile space (>= 34816 B)
#pragma unroll
        for (int i = 0; i < 4; i++) {
            const int rl = wm + i * 16 + g;
#pragma unroll
            for (int j = 0; j < 4; j++) {
                const int nl = wn + j * 8 + 2 * tg;
                const float2 bb = *(const float2*)(bias + (size_t)e * NCOLS + gn0 + nl);
                __half2 v0 = __floats2half2_rn(fmaxf(acc[i][j][0] + bb.x, 0.f),
                                               fmaxf(acc[i][j][1] + bb.y, 0.f));
                __half2 v1 = __floats2half2_rn(fmaxf(acc[i][j][2] + bb.x, 0.f),
                                               fmaxf(acc[i][j][3] + bb.y, 0.f));
                asm volatile("st.shared.b32 [%0], %1;"
                             :: "r"(ep + (uint32_t)(rl * ROWE + nl * 2)),
                                "r"(*(uint32_t*)&v0) : "memory");
                asm volatile("st.shared.b32 [%0], %1;"
                             :: "r"(ep + (uint32_t)((rl + 8) * ROWE + nl * 2)),
                                "r"(*(uint32_t*)&v1) : "memory");
            }
        }
        __syncthreads();
        const int r = tid >> 1, part = tid & 1;
        const int p = s_row[r];
        if (p >= 0) {
            __half* dst = g_h + (size_t)p * HIDDEN + gn0 + part * 64;
            const uint32_t src = ep + (uint32_t)(r * ROWE + part * 128);
#pragma unroll
            for (int q = 0; q < 8; q++) {
                uint4 d;
                asm volatile("ld.shared.v4.b32 {%0,%1,%2,%3}, [%4];"
                             : "=r"(d.x), "=r"(d.y), "=r"(d.z), "=r"(d.w)
                             : "r"(src + q * 16));
                *(uint4*)(dst + q * 8) = d;
            }
        }
    } else {
#pragma unroll
        for (int i = 0; i < 4; i++) {
            const int rl = wm + i * 16 + g;
            const int pl = s_row[rl],  ph = s_row[rl + 8];
            const float gl = s_gw[rl], gh2 = s_gw[rl + 8];
#pragma unroll
            for (int j = 0; j < 4; j++) {
                const int n = gn0 + wn + j * 8 + 2 * tg;
                const float2 bb = *(const float2*)(bias + (size_t)e * NCOLS + n);
                // two commutative addends onto 0.0f per element -> deterministic
                if (pl >= 0) {
                    float* op = out + (size_t)(pl >> 1) * DIM + n;
                    atomicAdd(op,     gl * (acc[i][j][0] + bb.x));
                    atomicAdd(op + 1, gl * (acc[i][j][1] + bb.y));
                }
                if (ph >= 0) {
                    float* op = out + (size_t)(ph >> 1) * DIM + n;
                    atomicAdd(op,     gh2 * (acc[i][j][2] + bb.x));
                    atomicAdd(op + 1, gh2 * (acc[i][j][3] + bb.y));
                }
            }
        }
    }
}

// ---------------- launch ----------------
static constexpr int SMEM_BYTES = 1280 + NSTAGE * STAGE_B;   // 108800

extern "C" void kernel_launch(void* const* d_in, const int* in_sizes, int n_in,
                              void* d_out, int out_size) {
    const float* x  = (const float*)d_in[0];
    const float* Wg = (const float*)d_in[1];
    const float* bg = (const float*)d_in[2];
    const float* W1 = (const float*)d_in[3];
    const float* b1 = (const float*)d_in[4];
    const float* W2 = (const float*)d_in[5];
    const float* b2 = (const float*)d_in[6];
    float* out = (float*)d_out;

    cudaFuncSetAttribute(moe_mma<0, DIM, HIDDEN, 5>,
                         cudaFuncAttributeMaxDynamicSharedMemorySize, SMEM_BYTES);
    cudaFuncSetAttribute(moe_mma<1, HIDDEN, DIM, 3>,
                         cudaFuncAttributeMaxDynamicSharedMemorySize, SMEM_BYTES);

    __half* W1h; cudaGetSymbolAddress((void**)&W1h, g_W1h);
    __half* W2h; cudaGetSymbolAddress((void**)&W2h, g_W2h);
    __half* xh;  cudaGetSymbolAddress((void**)&xh,  g_xh);
    __half* gh;  cudaGetSymbolAddress((void**)&gh,  g_h);

    zero_cnt_kernel<<<1, 32>>>();
    prep_kernel<<<GATE_BLOCKS + W1CVT_BLOCKS, 256>>>(x, Wg, bg, W1, out);
    moe_mma<0, DIM, HIDDEN, 5><<<G1_BLOCKS, NT, SMEM_BYTES>>>(
        xh, W1h, b1, nullptr, W2, W2h);
    moe_mma<1, HIDDEN, DIM, 3><<<32 * 8 * NEXP, NT, SMEM_BYTES>>>(
        gh, W2h, b2, out, nullptr, nullptr);
}

// round 15
// speedup vs baseline: 1.0059x; 1.0059x over previous
#include <cuda_runtime.h>
#include <cuda_fp16.h>
#include <math.h>
#include <stdint.h>

#define NTOK   4096
#define DIM    1024
#define NEXP   8
#define HIDDEN 4096

#define BM 128
#define BN 128
#define BKH 64            // K halfs per k-tile
#define NT 256
#define ROWA 144          // A SMEM row stride bytes
#define ROWBB 272         // B SMEM row stride bytes

#define TILE_A  (BM * ROWA)          // 18432
#define TILE_BB (BKH * ROWBB)        // 17408
#define STAGE_B (TILE_A + TILE_BB)   // 35840
#define NSTAGE  3

#define GATE_BLOCKS 512
#define W1CVT_BLOCKS 2048
#define G1_BLOCKS  8192              // 32m * 32n * 8e
#define CVT_CHUNKS 8192u             // W2 cvt: 8192 chunks x 1024 float4

// ---------------- scratch (__device__ statics — alloc-free) ----------------
// g_cnt / g_cvt start zero (static init) and are re-zeroed by GEMM2 each call,
// so every kernel_launch sees identical initial state (graph-replay safe).
__device__ int    g_cnt[NEXP];
__device__ int    g_cnt2[NEXP];       // stable snapshot for GEMM2
__device__ unsigned int g_cvt;
__device__ int    g_list[NEXP][NTOK];
__device__ float  g_gw[NEXP][NTOK];
__device__ __half g_xh[(size_t)NTOK * DIM];
__device__ __half g_h[(size_t)NTOK * 2 * HIDDEN];
__device__ __half g_W1h[(size_t)NEXP * DIM * HIDDEN];     // [e][k][n] fp16
__device__ __half g_W2h[(size_t)NEXP * HIDDEN * DIM];     // [e][k][n] fp16

// ---------------- helpers ----------------
__device__ __forceinline__ uint32_t smem_u32(const void* p) {
    uint32_t a;
    asm("{ .reg .u64 t; cvta.to.shared.u64 t, %1; cvt.u32.u64 %0, t; }" : "=r"(a) : "l"(p));
    return a;
}
__device__ __forceinline__ void cp_async16(uint32_t dst, const void* src) {
    asm volatile("cp.async.cg.shared.global [%0], [%1], 16;" :: "r"(dst), "l"(src));
}
#define CP_COMMIT() asm volatile("cp.async.commit_group;" ::: "memory")
#define CP_WAIT2()  asm volatile("cp.async.wait_group 2;" ::: "memory")

__device__ __forceinline__ void ldsm_x4(uint32_t* r, uint32_t addr) {
    asm volatile("ldmatrix.sync.aligned.m8n8.x4.shared.b16 {%0,%1,%2,%3}, [%4];"
                 : "=r"(r[0]), "=r"(r[1]), "=r"(r[2]), "=r"(r[3]) : "r"(addr));
}
__device__ __forceinline__ void ldsm_x4_t(uint32_t* r, uint32_t addr) {
    asm volatile("ldmatrix.sync.aligned.m8n8.x4.trans.shared.b16 {%0,%1,%2,%3}, [%4];"
                 : "=r"(r[0]), "=r"(r[1]), "=r"(r[2]), "=r"(r[3]) : "r"(addr));
}
__device__ __forceinline__ void mma_f16(float* d, const uint32_t* a, uint32_t b0, uint32_t b1) {
    asm volatile(
        "mma.sync.aligned.m16n8k16.row.col.f32.f16.f16.f32 "
        "{%0,%1,%2,%3}, {%4,%5,%6,%7}, {%8,%9}, {%0,%1,%2,%3};"
        : "+f"(d[0]), "+f"(d[1]), "+f"(d[2]), "+f"(d[3])
        : "r"(a[0]), "r"(a[1]), "r"(a[2]), "r"(a[3]), "r"(b0), "r"(b1));
}

// ---------------- prep: gate(+x cvt + out zero) | W1 straight cvt ----------------
__global__ void prep_kernel(const float* __restrict__ x,
                            const float* __restrict__ Wg,
                            const float* __restrict__ bg,
                            const float* __restrict__ W1,
                            float* __restrict__ out) {
    const int bid = blockIdx.x;
    const int tid = threadIdx.x;

    if (bid >= GATE_BLOCKS) {
        size_t base = (size_t)(bid - GATE_BLOCKS) * 16384 + (size_t)tid * 4;
#pragma unroll
        for (int j = 0; j < 16; j++) {
            size_t idx = base + (size_t)j * 1024;
            float4 v = *(const float4*)(W1 + idx);
            __half2 h0 = __floats2half2_rn(v.x, v.y);
            __half2 h1 = __floats2half2_rn(v.z, v.w);
            *(uint2*)(g_W1h + idx) = make_uint2(*(uint32_t*)&h0, *(uint32_t*)&h1);
        }
        return;
    }

    int warp = bid * 8 + (tid >> 5);
    int lane = tid & 31;

    const float4* xr4 = (const float4*)(x + (size_t)warp * DIM);
    __half2* xo = (__half2*)(g_xh + (size_t)warp * DIM);
    float4* oz = (float4*)(out + (size_t)warp * DIM);

    float acc[NEXP];
#pragma unroll
    for (int e = 0; e < NEXP; e++) acc[e] = 0.f;

#pragma unroll
    for (int it = 0; it < 8; it++) {
        int i4 = lane + it * 32;
        float4 xv = xr4[i4];
        xo[2 * i4]     = __floats2half2_rn(xv.x, xv.y);
        xo[2 * i4 + 1] = __floats2half2_rn(xv.z, xv.w);
        oz[i4] = make_float4(0.f, 0.f, 0.f, 0.f);
        const float* xs = (const float*)&xv;
#pragma unroll
        for (int c = 0; c < 4; c++) {
            float v = xs[c];
            const float4* w = reinterpret_cast<const float4*>(Wg + (size_t)(i4 * 4 + c) * NEXP);
            float4 w0 = w[0], w1 = w[1];
            acc[0] = fmaf(v, w0.x, acc[0]); acc[1] = fmaf(v, w0.y, acc[1]);
            acc[2] = fmaf(v, w0.z, acc[2]); acc[3] = fmaf(v, w0.w, acc[3]);
            acc[4] = fmaf(v, w1.x, acc[4]); acc[5] = fmaf(v, w1.y, acc[5]);
            acc[6] = fmaf(v, w1.z, acc[6]); acc[7] = fmaf(v, w1.w, acc[7]);
        }
    }
#pragma unroll
    for (int off = 16; off > 0; off >>= 1)
#pragma unroll
        for (int e = 0; e < NEXP; e++)
            acc[e] += __shfl_xor_sync(0xffffffffu, acc[e], off);

    if (lane == 0) {
        float lg[NEXP], mx = -1e30f;
#pragma unroll
        for (int e = 0; e < NEXP; e++) { lg[e] = acc[e] + bg[e]; mx = fmaxf(mx, lg[e]); }
        float p[NEXP], s = 0.f;
#pragma unroll
        for (int e = 0; e < NEXP; e++) { p[e] = expf(lg[e] - mx); s += p[e]; }
        float inv = 1.f / s;
        int i0 = 0;
#pragma unroll
        for (int e = 1; e < NEXP; e++) if (p[e] > p[i0]) i0 = e;
        int i1 = (i0 == 0) ? 1 : 0;
#pragma unroll
        for (int e = 0; e < NEXP; e++) if (e != i0 && p[e] > p[i1]) i1 = e;

        int pos0 = atomicAdd(&g_cnt[i0], 1);
        g_list[i0][pos0] = warp * 2 + 0;  g_gw[i0][pos0] = p[i0] * inv;
        int pos1 = atomicAdd(&g_cnt[i1], 1);
        g_list[i1][pos1] = warp * 2 + 1;  g_gw[i1][pos1] = p[i1] * inv;
    }
}

// ---------------- fp16 mma GEMM: 8 warps (64x32 tiles), 3-stage pipeline ----------------
// MODE 0: A = gathered g_xh, B = g_W1h, epi: half(relu(acc+b1)) -> g_h (scatter)
//         W2 fp32->fp16 cvt stuffed into the mainloop's idle issue slots.
//         bid0 snapshots g_cnt -> g_cnt2 (for GEMM2) before any reset.
// MODE 1: A = gathered g_h,  B = g_W2h (counts from g_cnt2),
//         epi: atomicAdd(out, gw*(acc+b2)); bid0 re-zeroes g_cnt/g_cvt for next call.
template<int MODE, int KDIM, int NCOLS, int LOGN>
__global__ void __launch_bounds__(NT, 2)
moe_mma(const __half* __restrict__ Asrc, const __half* __restrict__ Wh,
        const float* __restrict__ bias, float* __restrict__ out,
        const float* __restrict__ cvt_src, __half* __restrict__ cvt_dst) {
    const int bid = blockIdx.x;
    const int tid = threadIdx.x;

    if (bid == 0 && tid == 0) {
        if (MODE == 0) {
#pragma unroll
            for (int i = 0; i < NEXP; i++) g_cnt2[i] = g_cnt[i];
        } else {
#pragma unroll
            for (int i = 0; i < NEXP; i++) g_cnt[i] = 0;
            g_cvt = 0u;
        }
    }

    const int e   = bid >> (5 + LOGN);
    const int cnt = (MODE == 0) ? g_cnt[e] : g_cnt2[e];
    const int m0  = (bid & 31) * BM;
    if (m0 >= cnt) return;
    const int gn0 = ((bid >> 5) & ((1 << LOGN) - 1)) * BN;

    extern __shared__ char smem[];
    int*      s_row = (int*)smem;                 // [128] @ 0
    float*    s_gw  = (float*)(smem + 512);       // [128] @ 512
    unsigned* s_cvt = (unsigned*)(smem + 1024);   // @ 1024

    const int wid  = tid >> 5, lane = tid & 31;
    const int wm   = (wid >> 2) * 64;          // 0,64
    const int wn   = (wid & 3) * 32;           // 0,32,64,96
    const int g    = lane >> 2;
    const int tg   = lane & 3;

    for (int i = tid; i < BM; i += NT) {
        int r = m0 + i;
        if (r < cnt) { s_row[i] = g_list[e][r]; s_gw[i] = g_gw[e][r]; }
        else         { s_row[i] = -1;           s_gw[i] = 0.f; }
    }
    if (MODE == 0 && tid == 0) *s_cvt = atomicAdd(&g_cvt, 4u);
    __syncthreads();
    const unsigned cvt_base = (MODE == 0) ? *s_cvt : 0u;

    const uint32_t tiles_b = smem_u32(smem) + 1280;

    // A loader: 4 chunks of 16B; chunk i -> row lrow+32i, col c8
    const int lrow = tid >> 3, c8 = tid & 7;
    uint32_t a_off[4];
#pragma unroll
    for (int i = 0; i < 4; i++) {
        int p = s_row[lrow + i * 32];
        int arow = (p >= 0) ? (MODE == 0 ? (p >> 1) : p) : 0;
        a_off[i] = (uint32_t)arow * KDIM + c8 * 8;
    }
    const uint32_t a_dst0 = (uint32_t)(lrow * ROWA + c8 * 16);
    const uint32_t rstepA = 32 * ROWA;

    // B loader (K-major): 4 chunks; chunk i -> k-row brow+16i
    const int brow = tid >> 4, bc16 = tid & 15;
    const __half* b_base = Wh + ((size_t)e * KDIM + brow) * NCOLS + gn0 + bc16 * 8;
    const uint32_t b_dst0 = (uint32_t)(TILE_A + brow * ROWBB + bc16 * 16);
    const uint32_t bstep  = 16 * ROWBB;

    // LDSM lane addressing
    const uint32_t a_lane = (uint32_t)((lane & 15) * ROWA + (lane >> 4) * 16);
    const uint32_t bt_row = (uint32_t)(lane & 15);
    const uint32_t bt_col = (uint32_t)(((lane >> 4) & 1) * 16);

    float acc[4][4][4];
#pragma unroll
    for (int i = 0; i < 4; i++)
#pragma unroll
        for (int j = 0; j < 4; j++)
#pragma unroll
            for (int q = 0; q < 4; q++) acc[i][j][q] = 0.f;

    const int KT = KDIM / BKH;

    // prologue: stages 0 and 1
#pragma unroll
    for (int st = 0; st < 2; st++) {
        const uint32_t sb = tiles_b + st * STAGE_B;
        const int kk = st * BKH;
#pragma unroll
        for (int i = 0; i < 4; i++) {
            cp_async16(sb + a_dst0 + i * rstepA, Asrc + a_off[i] + kk);
            cp_async16(sb + b_dst0 + i * bstep,
                       b_base + (size_t)(kk + 16 * i) * NCOLS);
        }
        CP_COMMIT();
    }

    int stc = 0;
    int stp = 2;
#pragma unroll 1
    for (int t = 0; t < KT; ++t) {
        // ---- stuffed W2 cvt: load early (latency hides under the k-iter) ----
        float4 vv;
        bool do_cvt = false;
        size_t fidx = 0;
        if (MODE == 0) {
            unsigned ck = cvt_base + (unsigned)(t >> 2);
            if (ck < CVT_CHUNKS) {
                fidx = (size_t)ck * 1024 + (size_t)(t & 3) * 256 + tid;
                vv = ((const float4*)cvt_src)[fidx];
                do_cvt = true;
            }
        }

        if (t + 2 < KT) {
            const uint32_t sb = tiles_b + stp * STAGE_B;
            const int k2 = (t + 2) * BKH;
#pragma unroll
            for (int i = 0; i < 4; i++) {
                cp_async16(sb + a_dst0 + i * rstepA, Asrc + a_off[i] + k2);
                cp_async16(sb + b_dst0 + i * bstep,
                           b_base + (size_t)(k2 + 16 * i) * NCOLS);
            }
        }
        CP_COMMIT();
        CP_WAIT2();
        __syncthreads();

        const uint32_t As_b = tiles_b + stc * STAGE_B;
        const uint32_t Bs_b = As_b + TILE_A;
#pragma unroll
        for (int s = 0; s < 4; s++) {
            uint32_t af[4][4];
#pragma unroll
            for (int i = 0; i < 4; i++)
                ldsm_x4(af[i], As_b + (uint32_t)(wm + 16 * i) * ROWA + s * 32 + a_lane);
            uint32_t bf[2][4];
#pragma unroll
            for (int j2 = 0; j2 < 2; j2++)
                ldsm_x4_t(bf[j2], Bs_b + (uint32_t)(s * 16 + bt_row) * ROWBB
                                   + (uint32_t)(wn * 2 + j2 * 32) + bt_col);
#pragma unroll
            for (int i = 0; i < 4; i++)
#pragma unroll
                for (int j2 = 0; j2 < 2; j2++) {
                    mma_f16(acc[i][2 * j2],     af[i], bf[j2][0], bf[j2][1]);
                    mma_f16(acc[i][2 * j2 + 1], af[i], bf[j2][2], bf[j2][3]);
                }
        }

        // ---- stuffed W2 cvt: convert + store after compute ----
        if (MODE == 0 && do_cvt) {
            __half2 h0 = __floats2half2_rn(vv.x, vv.y);
            __half2 h1 = __floats2half2_rn(vv.z, vv.w);
            ((uint2*)cvt_dst)[fidx] = make_uint2(*(uint32_t*)&h0, *(uint32_t*)&h1);
        }

        __syncthreads();
        stc = (stc == NSTAGE - 1) ? 0 : stc + 1;
        stp = (stp == NSTAGE - 1) ? 0 : stp + 1;
    }

    // ---------------- epilogue (R13 direct form — staged variant regressed) ----------------
#pragma unroll
    for (int i = 0; i < 4; i++) {
        const int rl = wm + i * 16 + g;
        const int pl = s_row[rl],  ph = s_row[rl + 8];
        const float gl = s_gw[rl], gh2 = s_gw[rl + 8];
#pragma unroll
        for (int j = 0; j < 4; j++) {
            const int n = gn0 + wn + j * 8 + 2 * tg;
            const float2 bb = *(const float2*)(bias + (size_t)e * NCOLS + n);
            if (MODE == 0) {
                if (pl >= 0)
                    *(__half2*)(g_h + (size_t)pl * HIDDEN + n) =
                        __floats2half2_rn(fmaxf(acc[i][j][0] + bb.x, 0.f),
                                          fmaxf(acc[i][j][1] + bb.y, 0.f));
                if (ph >= 0)
                    *(__half2*)(g_h + (size_t)ph * HIDDEN + n) =
                        __floats2half2_rn(fmaxf(acc[i][j][2] + bb.x, 0.f),
                                          fmaxf(acc[i][j][3] + bb.y, 0.f));
            } else {
                // two commutative addends onto 0.0f per element -> deterministic
                if (pl >= 0) {
                    float* op = out + (size_t)(pl >> 1) * DIM + n;
                    atomicAdd(op,     gl * (acc[i][j][0] + bb.x));
                    atomicAdd(op + 1, gl * (acc[i][j][1] + bb.y));
                }
                if (ph >= 0) {
                    float* op = out + (size_t)(ph >> 1) * DIM + n;
                    atomicAdd(op,     gh2 * (acc[i][j][2] + bb.x));
                    atomicAdd(op + 1, gh2 * (acc[i][j][3] + bb.y));
                }
            }
        }
    }
}

// ---------------- launch ----------------
static constexpr int SMEM_BYTES = 1280 + NSTAGE * STAGE_B;   // 108800

extern "C" void kernel_launch(void* const* d_in, const int* in_sizes, int n_in,
                              void* d_out, int out_size) {
    const float* x  = (const float*)d_in[0];
    const float* Wg = (const float*)d_in[1];
    const float* bg = (const float*)d_in[2];
    const float* W1 = (const float*)d_in[3];
    const float* b1 = (const float*)d_in[4];
    const float* W2 = (const float*)d_in[5];
    const float* b2 = (const float*)d_in[6];
    float* out = (float*)d_out;

    cudaFuncSetAttribute(moe_mma<0, DIM, HIDDEN, 5>,
                         cudaFuncAttributeMaxDynamicSharedMemorySize, SMEM_BYTES);
    cudaFuncSetAttribute(moe_mma<1, HIDDEN, DIM, 3>,
                         cudaFuncAttributeMaxDynamicSharedMemorySize, SMEM_BYTES);

    __half* W1h; cudaGetSymbolAddress((void**)&W1h, g_W1h);
    __half* W2h; cudaGetSymbolAddress((void**)&W2h, g_W2h);
    __half* xh;  cudaGetSymbolAddress((void**)&xh,  g_xh);
    __half* gh;  cudaGetSymbolAddress((void**)&gh,  g_h);

    prep_kernel<<<GATE_BLOCKS + W1CVT_BLOCKS, 256>>>(x, Wg, bg, W1, out);
    moe_mma<0, DIM, HIDDEN, 5><<<G1_BLOCKS, NT, SMEM_BYTES>>>(
        xh, W1h, b1, nullptr, W2, W2h);
    moe_mma<1, HIDDEN, DIM, 3><<<32 * 8 * NEXP, NT, SMEM_BYTES>>>(
        gh, W2h, b2, out, nullptr, nullptr);
}

// round 16
// speedup vs baseline: 1.0550x; 1.0488x over previous
#include <cuda_runtime.h>
#include <cuda_fp16.h>
#include <math.h>
#include <stdint.h>

#define NTOK   4096
#define DIM    1024
#define NEXP   8
#define HIDDEN 4096

#define BM 128
#define BN 128
#define BKH 64            // K halfs per k-tile
#define NT 256
#define ROWA 144          // A SMEM row stride bytes
#define ROWBB 272         // B SMEM row stride bytes

#define TILE_A  (BM * ROWA)          // 18432
#define TILE_BB (BKH * ROWBB)        // 17408
#define STAGE_B (TILE_A + TILE_BB)   // 35840
#define NSTAGE  3

#define GATE_BLOCKS 512
#define W1CVT_BLOCKS 2048
#define G1_BLOCKS  8192              // 32m * 32n * 8e
#define CVT_CHUNKS 8192u             // W2 cvt: 8192 chunks x 1024 float4
#define WPITCH 1032                  // sW row pitch in floats (16B-aligned rows)

// ---------------- scratch (__device__ statics — alloc-free) ----------------
__device__ int    g_cnt[NEXP];
__device__ unsigned int g_cvt;
__device__ int    g_list[NEXP][NTOK];
__device__ float  g_gw[NEXP][NTOK];
__device__ __half g_xh[(size_t)NTOK * DIM];
__device__ __half g_h[(size_t)NTOK * 2 * HIDDEN];
__device__ __half g_W1h[(size_t)NEXP * DIM * HIDDEN];     // [e][k][n] fp16
__device__ __half g_W2h[(size_t)NEXP * HIDDEN * DIM];     // [e][k][n] fp16

// ---------------- helpers ----------------
__device__ __forceinline__ uint32_t smem_u32(const void* p) {
    uint32_t a;
    asm("{ .reg .u64 t; cvta.to.shared.u64 t, %1; cvt.u32.u64 %0, t; }" : "=r"(a) : "l"(p));
    return a;
}
__device__ __forceinline__ void cp_async16(uint32_t dst, const void* src) {
    asm volatile("cp.async.cg.shared.global [%0], [%1], 16;" :: "r"(dst), "l"(src));
}
#define CP_COMMIT() asm volatile("cp.async.commit_group;" ::: "memory")
#define CP_WAIT2()  asm volatile("cp.async.wait_group 2;" ::: "memory")

__device__ __forceinline__ void ldsm_x4(uint32_t* r, uint32_t addr) {
    asm volatile("ldmatrix.sync.aligned.m8n8.x4.shared.b16 {%0,%1,%2,%3}, [%4];"
                 : "=r"(r[0]), "=r"(r[1]), "=r"(r[2]), "=r"(r[3]) : "r"(addr));
}
__device__ __forceinline__ void ldsm_x4_t(uint32_t* r, uint32_t addr) {
    asm volatile("ldmatrix.sync.aligned.m8n8.x4.trans.shared.b16 {%0,%1,%2,%3}, [%4];"
                 : "=r"(r[0]), "=r"(r[1]), "=r"(r[2]), "=r"(r[3]) : "r"(addr));
}
__device__ __forceinline__ void mma_f16(float* d, const uint32_t* a, uint32_t b0, uint32_t b1) {
    asm volatile(
        "mma.sync.aligned.m16n8k16.row.col.f32.f16.f16.f32 "
        "{%0,%1,%2,%3}, {%4,%5,%6,%7}, {%8,%9}, {%0,%1,%2,%3};"
        : "+f"(d[0]), "+f"(d[1]), "+f"(d[2]), "+f"(d[3])
        : "r"(a[0]), "r"(a[1]), "r"(a[2]), "r"(a[3]), "r"(b0), "r"(b1));
}

// ---------------- kernel 0: reset counters ----------------
__global__ void zero_cnt_kernel() {
    if (threadIdx.x < NEXP) g_cnt[threadIdx.x] = 0;
    if (threadIdx.x == 0)   g_cvt = 0u;
}

// ---------------- prep: gate(+x cvt + out zero, Wg staged in SMEM) | W1 cvt ----------------
__global__ void prep_kernel(const float* __restrict__ x,
                            const float* __restrict__ Wg,
                            const float* __restrict__ bg,
                            const float* __restrict__ W1,
                            float* __restrict__ out) {
    const int bid = blockIdx.x;
    const int tid = threadIdx.x;

    if (bid >= GATE_BLOCKS) {
        size_t base = (size_t)(bid - GATE_BLOCKS) * 16384 + (size_t)tid * 4;
#pragma unroll
        for (int j = 0; j < 16; j++) {
            size_t idx = base + (size_t)j * 1024;
            float4 v = *(const float4*)(W1 + idx);
            __half2 h0 = __floats2half2_rn(v.x, v.y);
            __half2 h1 = __floats2half2_rn(v.z, v.w);
            *(uint2*)(g_W1h + idx) = make_uint2(*(uint32_t*)&h0, *(uint32_t*)&h1);
        }
        return;
    }

    // ---- gate role ----
    __shared__ float sW[NEXP][WPITCH];     // Wg transposed: sW[e][d]

    // stage Wg (coalesced global read; conflict-free scalar STS across d)
    for (int d = tid; d < DIM; d += 256) {
        float4 w0 = *(const float4*)(Wg + (size_t)d * NEXP);
        float4 w1 = *(const float4*)(Wg + (size_t)d * NEXP + 4);
        sW[0][d] = w0.x; sW[1][d] = w0.y; sW[2][d] = w0.z; sW[3][d] = w0.w;
        sW[4][d] = w1.x; sW[5][d] = w1.y; sW[6][d] = w1.z; sW[7][d] = w1.w;
    }
    __syncthreads();

    int warp = bid * 8 + (tid >> 5);
    int lane = tid & 31;

    const float4* xr4 = (const float4*)(x + (size_t)warp * DIM);
    __half2* xo = (__half2*)(g_xh + (size_t)warp * DIM);
    float4* oz = (float4*)(out + (size_t)warp * DIM);

    float acc[NEXP];
#pragma unroll
    for (int e = 0; e < NEXP; e++) acc[e] = 0.f;

#pragma unroll
    for (int it = 0; it < 8; it++) {
        int i4 = lane + it * 32;
        float4 xv = xr4[i4];
        xo[2 * i4]     = __floats2half2_rn(xv.x, xv.y);
        xo[2 * i4 + 1] = __floats2half2_rn(xv.z, xv.w);
        oz[i4] = make_float4(0.f, 0.f, 0.f, 0.f);
#pragma unroll
        for (int e = 0; e < NEXP; e++) {
            float4 w = *(const float4*)&sW[e][4 * i4];   // conflict-free LDS.128
            // ascending-d fma chain == previous accumulation order (bitwise identical)
            acc[e] = fmaf(xv.x, w.x, acc[e]);
            acc[e] = fmaf(xv.y, w.y, acc[e]);
            acc[e] = fmaf(xv.z, w.z, acc[e]);
            acc[e] = fmaf(xv.w, w.w, acc[e]);
        }
    }
#pragma unroll
    for (int off = 16; off > 0; off >>= 1)
#pragma unroll
        for (int e = 0; e < NEXP; e++)
            acc[e] += __shfl_xor_sync(0xffffffffu, acc[e], off);

    if (lane == 0) {
        float lg[NEXP], mx = -1e30f;
#pragma unroll
        for (int e = 0; e < NEXP; e++) { lg[e] = acc[e] + bg[e]; mx = fmaxf(mx, lg[e]); }
        float p[NEXP], s = 0.f;
#pragma unroll
        for (int e = 0; e < NEXP; e++) { p[e] = expf(lg[e] - mx); s += p[e]; }
        float inv = 1.f / s;
        int i0 = 0;
#pragma unroll
        for (int e = 1; e < NEXP; e++) if (p[e] > p[i0]) i0 = e;
        int i1 = (i0 == 0) ? 1 : 0;
#pragma unroll
        for (int e = 0; e < NEXP; e++) if (e != i0 && p[e] > p[i1]) i1 = e;

        int pos0 = atomicAdd(&g_cnt[i0], 1);
        g_list[i0][pos0] = warp * 2 + 0;  g_gw[i0][pos0] = p[i0] * inv;
        int pos1 = atomicAdd(&g_cnt[i1], 1);
        g_list[i1][pos1] = warp * 2 + 1;  g_gw[i1][pos1] = p[i1] * inv;
    }
}

// ---------------- fp16 mma GEMM: 8 warps (64x32 tiles), 3-stage pipeline ----------------
// MODE 0: A = gathered g_xh, B = g_W1h, epi: half(relu(acc+b1)) -> g_h (scatter)
//         W2 fp32->fp16 cvt stuffed into the mainloop's idle issue slots.
// MODE 1: A = gathered g_h,  B = g_W2h, epi: atomicAdd(out, gw*(acc+b2))
template<int MODE, int KDIM, int NCOLS, int LOGN>
__global__ void __launch_bounds__(NT, 2)
moe_mma(const __half* __restrict__ Asrc, const __half* __restrict__ Wh,
        const float* __restrict__ bias, float* __restrict__ out,
        const float* __restrict__ cvt_src, __half* __restrict__ cvt_dst) {
    const int bid = blockIdx.x;
    const int tid = threadIdx.x;

    const int e   = bid >> (5 + LOGN);
    const int cnt = g_cnt[e];
    const int m0  = (bid & 31) * BM;
    if (m0 >= cnt) return;
    const int gn0 = ((bid >> 5) & ((1 << LOGN) - 1)) * BN;

    extern __shared__ char smem[];
    int*      s_row = (int*)smem;                 // [128] @ 0
    float*    s_gw  = (float*)(smem + 512);       // [128] @ 512
    unsigned* s_cvt = (unsigned*)(smem + 1024);   // @ 1024

    const int wid  = tid >> 5, lane = tid & 31;
    const int wm   = (wid >> 2) * 64;          // 0,64
    const int wn   = (wid & 3) * 32;           // 0,32,64,96
    const int g    = lane >> 2;
    const int tg   = lane & 3;

    for (int i = tid; i < BM; i += NT) {
        int r = m0 + i;
        if (r < cnt) { s_row[i] = g_list[e][r]; s_gw[i] = g_gw[e][r]; }
        else         { s_row[i] = -1;           s_gw[i] = 0.f; }
    }
    if (MODE == 0 && tid == 0) *s_cvt = atomicAdd(&g_cvt, 4u);
    __syncthreads();
    const unsigned cvt_base = (MODE == 0) ? *s_cvt : 0u;

    const uint32_t tiles_b = smem_u32(smem) + 1280;

    // A loader: 4 chunks of 16B; chunk i -> row lrow+32i, col c8
    const int lrow = tid >> 3, c8 = tid & 7;
    uint32_t a_off[4];
#pragma unroll
    for (int i = 0; i < 4; i++) {
        int p = s_row[lrow + i * 32];
        int arow = (p >= 0) ? (MODE == 0 ? (p >> 1) : p) : 0;
        a_off[i] = (uint32_t)arow * KDIM + c8 * 8;
    }
    const uint32_t a_dst0 = (uint32_t)(lrow * ROWA + c8 * 16);
    const uint32_t rstepA = 32 * ROWA;

    // B loader (K-major): 4 chunks; chunk i -> k-row brow+16i
    const int brow = tid >> 4, bc16 = tid & 15;
    const __half* b_base = Wh + ((size_t)e * KDIM + brow) * NCOLS + gn0 + bc16 * 8;
    const uint32_t b_dst0 = (uint32_t)(TILE_A + brow * ROWBB + bc16 * 16);
    const uint32_t bstep  = 16 * ROWBB;

    // LDSM lane addressing
    const uint32_t a_lane = (uint32_t)((lane & 15) * ROWA + (lane >> 4) * 16);
    const uint32_t bt_row = (uint32_t)(lane & 15);
    const uint32_t bt_col = (uint32_t)(((lane >> 4) & 1) * 16);

    float acc[4][4][4];
#pragma unroll
    for (int i = 0; i < 4; i++)
#pragma unroll
        for (int j = 0; j < 4; j++)
#pragma unroll
            for (int q = 0; q < 4; q++) acc[i][j][q] = 0.f;

    const int KT = KDIM / BKH;

    // prologue: stages 0 and 1
#pragma unroll
    for (int st = 0; st < 2; st++) {
        const uint32_t sb = tiles_b + st * STAGE_B;
        const int kk = st * BKH;
#pragma unroll
        for (int i = 0; i < 4; i++) {
            cp_async16(sb + a_dst0 + i * rstepA, Asrc + a_off[i] + kk);
            cp_async16(sb + b_dst0 + i * bstep,
                       b_base + (size_t)(kk + 16 * i) * NCOLS);
        }
        CP_COMMIT();
    }

    int stc = 0;
    int stp = 2;
#pragma unroll 1
    for (int t = 0; t < KT; ++t) {
        // ---- stuffed W2 cvt: load early (latency hides under the k-iter) ----
        float4 vv;
        bool do_cvt = false;
        size_t fidx = 0;
        if (MODE == 0) {
            unsigned ck = cvt_base + (unsigned)(t >> 2);
            if (ck < CVT_CHUNKS) {
                fidx = (size_t)ck * 1024 + (size_t)(t & 3) * 256 + tid;
                vv = ((const float4*)cvt_src)[fidx];
                do_cvt = true;
            }
        }

        if (t + 2 < KT) {
            const uint32_t sb = tiles_b + stp * STAGE_B;
            const int k2 = (t + 2) * BKH;
#pragma unroll
            for (int i = 0; i < 4; i++) {
                cp_async16(sb + a_dst0 + i * rstepA, Asrc + a_off[i] + k2);
                cp_async16(sb + b_dst0 + i * bstep,
                           b_base + (size_t)(k2 + 16 * i) * NCOLS);
            }
        }
        CP_COMMIT();
        CP_WAIT2();
        __syncthreads();

        const uint32_t As_b = tiles_b + stc * STAGE_B;
        const uint32_t Bs_b = As_b + TILE_A;
#pragma unroll
        for (int s = 0; s < 4; s++) {
            uint32_t af[4][4];
#pragma unroll
            for (int i = 0; i < 4; i++)
                ldsm_x4(af[i], As_b + (uint32_t)(wm + 16 * i) * ROWA + s * 32 + a_lane);
            uint32_t bf[2][4];
#pragma unroll
            for (int j2 = 0; j2 < 2; j2++)
                ldsm_x4_t(bf[j2], Bs_b + (uint32_t)(s * 16 + bt_row) * ROWBB
                                   + (uint32_t)(wn * 2 + j2 * 32) + bt_col);
#pragma unroll
            for (int i = 0; i < 4; i++)
#pragma unroll
                for (int j2 = 0; j2 < 2; j2++) {
                    mma_f16(acc[i][2 * j2],     af[i], bf[j2][0], bf[j2][1]);
                    mma_f16(acc[i][2 * j2 + 1], af[i], bf[j2][2], bf[j2][3]);
                }
        }

        // ---- stuffed W2 cvt: convert + store after compute ----
        if (MODE == 0 && do_cvt) {
            __half2 h0 = __floats2half2_rn(vv.x, vv.y);
            __half2 h1 = __floats2half2_rn(vv.z, vv.w);
            ((uint2*)cvt_dst)[fidx] = make_uint2(*(uint32_t*)&h0, *(uint32_t*)&h1);
        }

        __syncthreads();
        stc = (stc == NSTAGE - 1) ? 0 : stc + 1;
        stp = (stp == NSTAGE - 1) ? 0 : stp + 1;
    }

    // ---------------- epilogue (direct scatter — proven fastest) ----------------
#pragma unroll
    for (int i = 0; i < 4; i++) {
        const int rl = wm + i * 16 + g;
        const int pl = s_row[rl],  ph = s_row[rl + 8];
        const float gl = s_gw[rl], gh2 = s_gw[rl + 8];
#pragma unroll
        for (int j = 0; j < 4; j++) {
            const int n = gn0 + wn + j * 8 + 2 * tg;
            const float2 bb = *(const float2*)(bias + (size_t)e * NCOLS + n);
            if (MODE == 0) {
                if (pl >= 0)
                    *(__half2*)(g_h + (size_t)pl * HIDDEN + n) =
                        __floats2half2_rn(fmaxf(acc[i][j][0] + bb.x, 0.f),
                                          fmaxf(acc[i][j][1] + bb.y, 0.f));
                if (ph >= 0)
                    *(__half2*)(g_h + (size_t)ph * HIDDEN + n) =
                        __floats2half2_rn(fmaxf(acc[i][j][2] + bb.x, 0.f),
                                          fmaxf(acc[i][j][3] + bb.y, 0.f));
            } else {
                // two commutative addends onto 0.0f per element -> deterministic
                if (pl >= 0) {
                    float* op = out + (size_t)(pl >> 1) * DIM + n;
                    atomicAdd(op,     gl * (acc[i][j][0] + bb.x));
                    atomicAdd(op + 1, gl * (acc[i][j][1] + bb.y));
                }
                if (ph >= 0) {
                    float* op = out + (size_t)(ph >> 1) * DIM + n;
                    atomicAdd(op,     gh2 * (acc[i][j][2] + bb.x));
                    atomicAdd(op + 1, gh2 * (acc[i][j][3] + bb.y));
                }
            }
        }
    }
}

// ---------------- launch ----------------
static constexpr int SMEM_BYTES = 1280 + NSTAGE * STAGE_B;   // 108800

extern "C" void kernel_launch(void* const* d_in, const int* in_sizes, int n_in,
                              void* d_out, int out_size) {
    const float* x  = (const float*)d_in[0];
    const float* Wg = (const float*)d_in[1];
    const float* bg = (const float*)d_in[2];
    const float* W1 = (const float*)d_in[3];
    const float* b1 = (const float*)d_in[4];
    const float* W2 = (const float*)d_in[5];
    const float* b2 = (const float*)d_in[6];
    float* out = (float*)d_out;

    cudaFuncSetAttribute(moe_mma<0, DIM, HIDDEN, 5>,
                         cudaFuncAttributeMaxDynamicSharedMemorySize, SMEM_BYTES);
    cudaFuncSetAttribute(moe_mma<1, HIDDEN, DIM, 3>,
                         cudaFuncAttributeMaxDynamicSharedMemorySize, SMEM_BYTES);

    __half* W1h; cudaGetSymbolAddress((void**)&W1h, g_W1h);
    __half* W2h; cudaGetSymbolAddress((void**)&W2h, g_W2h);
    __half* xh;  cudaGetSymbolAddress((void**)&xh,  g_xh);
    __half* gh;  cudaGetSymbolAddress((void**)&gh,  g_h);

    zero_cnt_kernel<<<1, 32>>>();
    prep_kernel<<<GATE_BLOCKS + W1CVT_BLOCKS, 256>>>(x, Wg, bg, W1, out);
    moe_mma<0, DIM, HIDDEN, 5><<<G1_BLOCKS, NT, SMEM_BYTES>>>(
        xh, W1h, b1, nullptr, W2, W2h);
    moe_mma<1, HIDDEN, DIM, 3><<<32 * 8 * NEXP, NT, SMEM_BYTES>>>(
        gh, W2h, b2, out, nullptr, nullptr);
}